// round 1
// baseline (speedup 1.0000x reference)
#include <cuda_runtime.h>
#include <cuda_bf16.h>

// ---------------------------------------------------------------------------
// MPNN: 4-layer message passing GNN.
//   Key algebra:
//     m_in @ W1 = h[tgt]@W1a + h[src]@W1b + ea@W1c   (node GEMMs + per-edge ea proj)
//     mean_e(relu(z)@W2 + b2) = mean_e(relu(z))@W2 + b2   (deg>0; 0 otherwise)
//   CSR-by-tgt built in-graph each launch (counting sort), warp-per-node edge
//   kernel (no float atomics), fp32 throughout.
// ---------------------------------------------------------------------------

#define NN   50000
#define EE   800000
#define NFD  64
#define EFD  32
#define HH   96
#define OUTD 64
#define LL   4
#define GG   64

// ------------------------------- scratch -----------------------------------
// fbuf: h, h2, tmp, PT, PS, AGG, AGGM  (each NN*HH) + gmean + ghid
#define NH (NN * HH)
__device__ float d_fbuf[7 * NH + 2 * GG * HH];
// ibuf: deg[NN], rowptr[NN+1], cursor[NN], srcs[EE], eids[EE], gcnt[GG+1], gstart[GG+1]
__device__ int d_ibuf[NN + (NN + 1) + NN + EE + EE + (GG + 1) + (GG + 1)];

// ------------------------------- kernels -----------------------------------

__global__ void hist_kernel(const int* __restrict__ idx, int* __restrict__ cnt, int n) {
    int i = blockIdx.x * blockDim.x + threadIdx.x;
    if (i < n) atomicAdd(&cnt[idx[i]], 1);
}

__global__ void scatter_kernel(const int* __restrict__ src, const int* __restrict__ tgt,
                               int* __restrict__ cursor, int* __restrict__ srcs,
                               int* __restrict__ eids, int n) {
    int e = blockIdx.x * blockDim.x + threadIdx.x;
    if (e < n) {
        int p = atomicAdd(&cursor[tgt[e]], 1);
        srcs[p] = src[e];
        eids[p] = e;
    }
}

// exclusive scan (single block, loops over chunks); out[n] = total
__global__ void scan_kernel(const int* __restrict__ in, int* __restrict__ out, int n) {
    __shared__ int sums[32];
    int lane = threadIdx.x & 31, wid = threadIdx.x >> 5;
    int nwarp = blockDim.x >> 5;
    int offset = 0;
    for (int base = 0; base < n; base += blockDim.x) {
        int i = base + threadIdx.x;
        int v = (i < n) ? in[i] : 0;
        int x = v;
        #pragma unroll
        for (int d = 1; d < 32; d <<= 1) {
            int y = __shfl_up_sync(0xffffffffu, x, d);
            if (lane >= d) x += y;
        }
        if (lane == 31) sums[wid] = x;
        __syncthreads();
        if (wid == 0) {
            int s = (lane < nwarp) ? sums[lane] : 0;
            #pragma unroll
            for (int d = 1; d < 32; d <<= 1) {
                int y = __shfl_up_sync(0xffffffffu, s, d);
                if (lane >= d) s += y;
            }
            sums[lane] = s;
        }
        __syncthreads();
        int warp_off = (wid > 0) ? sums[wid - 1] : 0;
        if (i < n) out[i] = offset + warp_off + x - v;
        int total = sums[nwarp - 1];
        __syncthreads();
        offset += total;
    }
    if (threadIdx.x == 0) out[n] = offset;
}

// C[M,Ncols] = act(A@W + b); A columns k<K1 from A1 (lda1), else A2 (lda2).
// Block tile 128x96, BK=32, thread tile 8x6 (256 threads).
__global__ void __launch_bounds__(256) gemm_kernel(
    const float* __restrict__ A1, int lda1,
    const float* __restrict__ A2, int lda2, int K1, int K,
    const float* __restrict__ W, int ldW,
    const float* __restrict__ bias,
    float* __restrict__ C, int ldC,
    int M, int Ncols, int do_relu, const int* __restrict__ rowmask) {
    __shared__ float As[32][132];
    __shared__ float Ws[32][96];
    int tid = threadIdx.x;
    int tx = tid & 15, ty = tid >> 4;
    int bm0 = blockIdx.x * 128, bn0 = blockIdx.y * 96;
    float acc[8][6];
    #pragma unroll
    for (int i = 0; i < 8; i++)
        #pragma unroll
        for (int j = 0; j < 6; j++) acc[i][j] = 0.f;

    for (int k0 = 0; k0 < K; k0 += 32) {
        #pragma unroll
        for (int i = 0; i < 4; i++) {
            int idx = tid + 256 * i;
            int r = idx >> 3, k4 = (idx & 7) << 2;
            int gr = bm0 + r, gk = k0 + k4;
            float4 v = make_float4(0.f, 0.f, 0.f, 0.f);
            if (gr < M) {
                if (gk < K1) v = *(const float4*)(A1 + gr * lda1 + gk);
                else         v = *(const float4*)(A2 + gr * lda2 + (gk - K1));
            }
            As[k4][r] = v.x; As[k4 + 1][r] = v.y; As[k4 + 2][r] = v.z; As[k4 + 3][r] = v.w;
        }
        #pragma unroll
        for (int i = 0; i < 3; i++) {
            int idx = tid + 256 * i;
            int kk = idx / 24, n4 = (idx % 24) << 2;
            int gn = bn0 + n4;
            float4 v = make_float4(0.f, 0.f, 0.f, 0.f);
            if (gn < Ncols) v = *(const float4*)(W + (k0 + kk) * ldW + gn);
            Ws[kk][n4] = v.x; Ws[kk][n4 + 1] = v.y; Ws[kk][n4 + 2] = v.z; Ws[kk][n4 + 3] = v.w;
        }
        __syncthreads();
        #pragma unroll
        for (int kk = 0; kk < 32; kk++) {
            float4 a0 = *(const float4*)&As[kk][ty * 8];
            float4 a1 = *(const float4*)&As[kk][ty * 8 + 4];
            float a_[8] = {a0.x, a0.y, a0.z, a0.w, a1.x, a1.y, a1.z, a1.w};
            float w_[6];
            #pragma unroll
            for (int j = 0; j < 6; j++) w_[j] = Ws[kk][tx + 16 * j];
            #pragma unroll
            for (int i = 0; i < 8; i++)
                #pragma unroll
                for (int j = 0; j < 6; j++)
                    acc[i][j] = fmaf(a_[i], w_[j], acc[i][j]);
        }
        __syncthreads();
    }

    #pragma unroll
    for (int i = 0; i < 8; i++) {
        int row = bm0 + ty * 8 + i;
        if (row >= M) continue;
        bool zero_row = (rowmask != nullptr) && (rowmask[row] == 0);
        #pragma unroll
        for (int j = 0; j < 6; j++) {
            int col = bn0 + tx + 16 * j;
            if (col < Ncols) {
                float v = acc[i][j] + (bias ? bias[col] : 0.f);
                if (do_relu) v = fmaxf(v, 0.f);
                if (zero_row) v = 0.f;
                C[row * ldC + col] = v;
            }
        }
    }
}

// warp-per-node: z_e = relu(PT[n] + PS[src] + ea@W1c), AGG[n] = mean_e z_e
__global__ void __launch_bounds__(256) edge_kernel(
    const float* __restrict__ PT, const float* __restrict__ PS,
    const float* __restrict__ EA, const float* __restrict__ Wc,
    const int* __restrict__ rowptr, const int* __restrict__ srcs,
    const int* __restrict__ eids, float* __restrict__ AGG, int n_nodes) {
    int lane = threadIdx.x & 31;
    int warp = threadIdx.x >> 5;
    int node = blockIdx.x * 8 + warp;

    // W1c[32,96] held in registers: lane owns features lane, lane+32, lane+64
    float w0[32], w1[32], w2[32];
    #pragma unroll
    for (int k = 0; k < 32; k++) {
        w0[k] = Wc[k * 96 + lane];
        w1[k] = Wc[k * 96 + lane + 32];
        w2[k] = Wc[k * 96 + lane + 64];
    }
    if (node >= n_nodes) return;
    int beg = rowptr[node], end = rowptr[node + 1];
    float pt0 = PT[node * 96 + lane];
    float pt1 = PT[node * 96 + lane + 32];
    float pt2 = PT[node * 96 + lane + 64];
    float acc0 = 0.f, acc1 = 0.f, acc2 = 0.f;
    for (int i = beg; i < end; i++) {
        int s = srcs[i];
        int e = eids[i];
        float ea = EA[e * 32 + lane];
        float v0 = pt0 + PS[s * 96 + lane];
        float v1 = pt1 + PS[s * 96 + lane + 32];
        float v2 = pt2 + PS[s * 96 + lane + 64];
        #pragma unroll
        for (int k = 0; k < 32; k++) {
            float a = __shfl_sync(0xffffffffu, ea, k);
            v0 = fmaf(a, w0[k], v0);
            v1 = fmaf(a, w1[k], v1);
            v2 = fmaf(a, w2[k], v2);
        }
        acc0 += fmaxf(v0, 0.f);
        acc1 += fmaxf(v1, 0.f);
        acc2 += fmaxf(v2, 0.f);
    }
    float inv = 1.f / (float)max(end - beg, 1);
    AGG[node * 96 + lane]      = acc0 * inv;
    AGG[node * 96 + lane + 32] = acc1 * inv;
    AGG[node * 96 + lane + 64] = acc2 * inv;
}

// block-per-graph mean pool (batch is sorted -> contiguous ranges)
__global__ void pool_kernel(const float* __restrict__ h, const int* __restrict__ gstart,
                            float* __restrict__ gmean) {
    int g = blockIdx.x;
    int f = threadIdx.x;  // 96 threads
    int beg = gstart[g], end = gstart[g + 1];
    float s0 = 0.f, s1 = 0.f;
    int r = beg;
    for (; r + 1 < end; r += 2) {
        s0 += h[r * 96 + f];
        s1 += h[(r + 1) * 96 + f];
    }
    if (r < end) s0 += h[r * 96 + f];
    float inv = 1.f / (float)max(end - beg, 1);
    gmean[g * 96 + f] = (s0 + s1) * inv;
}

// ------------------------------- host --------------------------------------

static void launch_gemm(const float* A1, int lda1, const float* A2, int lda2,
                        int K1, int K, const float* W, int ldW, const float* bias,
                        float* C, int ldC, int M, int Ncols, int relu,
                        const int* mask, cudaStream_t s) {
    dim3 grid((M + 127) / 128, (Ncols + 95) / 96);
    gemm_kernel<<<grid, 256, 0, s>>>(A1, lda1, A2, lda2, K1, K, W, ldW, bias,
                                     C, ldC, M, Ncols, relu, mask);
}

extern "C" void kernel_launch(void* const* d_in, const int* in_sizes, int n_in,
                              void* d_out, int out_size) {
    const float* x         = (const float*)d_in[0];
    const float* edge_attr = (const float*)d_in[1];
    const int*   edge_index= (const int*)d_in[2];
    const int*   batch     = (const int*)d_in[3];
    const float* emb_w1 = (const float*)d_in[4];
    const float* emb_b1 = (const float*)d_in[5];
    const float* emb_w2 = (const float*)d_in[6];
    const float* emb_b2 = (const float*)d_in[7];
    const float* msg_w1 = (const float*)d_in[8];
    const float* msg_b1 = (const float*)d_in[9];
    const float* msg_w2 = (const float*)d_in[10];
    const float* msg_b2 = (const float*)d_in[11];
    const float* upd_w1 = (const float*)d_in[12];
    const float* upd_b1 = (const float*)d_in[13];
    const float* upd_w2 = (const float*)d_in[14];
    const float* upd_b2 = (const float*)d_in[15];
    const float* head_w1 = (const float*)d_in[16];
    const float* head_b1 = (const float*)d_in[17];
    const float* head_w2 = (const float*)d_in[18];
    const float* head_b2 = (const float*)d_in[19];

    float* fbuf = nullptr;
    int*   ibuf = nullptr;
    cudaGetSymbolAddress((void**)&fbuf, d_fbuf);
    cudaGetSymbolAddress((void**)&ibuf, d_ibuf);

    float* h    = fbuf + 0 * NH;
    float* h2   = fbuf + 1 * NH;
    float* tmp  = fbuf + 2 * NH;
    float* PT   = fbuf + 3 * NH;
    float* PS   = fbuf + 4 * NH;
    float* AGG  = fbuf + 5 * NH;
    float* AGGM = fbuf + 6 * NH;
    float* gmean = fbuf + 7 * NH;
    float* ghid  = gmean + GG * HH;

    int* deg    = ibuf;
    int* rowptr = deg + NN;
    int* cursor = rowptr + NN + 1;
    int* srcs   = cursor + NN;
    int* eids   = srcs + EE;
    int* gcnt   = eids + EE;
    int* gstart = gcnt + GG + 1;

    const int* src = edge_index;       // edge_index[0]
    const int* tgt = edge_index + EE;  // edge_index[1]

    cudaStream_t s = 0;

    // --- CSR by tgt + graph boundaries (recomputed each replay) ---
    cudaMemsetAsync(deg, 0, NN * sizeof(int), s);
    cudaMemsetAsync(gcnt, 0, (GG + 1) * sizeof(int), s);
    hist_kernel<<<(EE + 255) / 256, 256, 0, s>>>(tgt, deg, EE);
    scan_kernel<<<1, 1024, 0, s>>>(deg, rowptr, NN);
    cudaMemcpyAsync(cursor, rowptr, NN * sizeof(int), cudaMemcpyDeviceToDevice, s);
    scatter_kernel<<<(EE + 255) / 256, 256, 0, s>>>(src, tgt, cursor, srcs, eids, EE);
    hist_kernel<<<(NN + 255) / 256, 256, 0, s>>>(batch, gcnt, NN);
    scan_kernel<<<1, 1024, 0, s>>>(gcnt, gstart, GG);

    // --- embed: h = mlp2(x) ---
    launch_gemm(x, NFD, nullptr, 0, NFD, NFD, emb_w1, HH, emb_b1, tmp, HH, NN, HH, 1, nullptr, s);
    launch_gemm(tmp, HH, nullptr, 0, HH, HH, emb_w2, HH, emb_b2, h, HH, NN, HH, 0, nullptr, s);

    float* hc = h;
    float* hn = h2;
    for (int l = 0; l < LL; l++) {
        const float* mw1 = msg_w1 + l * (2 * HH + EFD) * HH;   // [224,96]
        const float* W1a = mw1;                 // rows 0..95   (h[tgt])
        const float* W1b = mw1 + HH * HH;       // rows 96..191 (h[src])
        const float* W1c = mw1 + 2 * HH * HH;   // rows 192..223 (edge_attr)
        // PT = h@W1a + b1 ; PS = h@W1b
        launch_gemm(hc, HH, nullptr, 0, HH, HH, W1a, HH, msg_b1 + l * HH, PT, HH, NN, HH, 0, nullptr, s);
        launch_gemm(hc, HH, nullptr, 0, HH, HH, W1b, HH, nullptr, PS, HH, NN, HH, 0, nullptr, s);
        // AGG[n] = mean_e relu(PT[n]+PS[src]+ea@W1c)
        edge_kernel<<<(NN + 7) / 8, 256, 0, s>>>(PT, PS, edge_attr, W1c, rowptr, srcs, eids, AGG, NN);
        // AGGM = AGG@msg_w2 + msg_b2 (0 for deg==0 rows)
        launch_gemm(AGG, HH, nullptr, 0, HH, HH, msg_w2 + l * HH * HH, HH, msg_b2 + l * HH,
                    AGGM, HH, NN, HH, 0, deg, s);
        // update: hn = relu([hc|AGGM]@upd_w1 + b1)@upd_w2 + b2
        launch_gemm(hc, HH, AGGM, HH, HH, 2 * HH, upd_w1 + l * 2 * HH * HH, HH,
                    upd_b1 + l * HH, tmp, HH, NN, HH, 1, nullptr, s);
        launch_gemm(tmp, HH, nullptr, 0, HH, HH, upd_w2 + l * HH * HH, HH, upd_b2 + l * HH,
                    hn, HH, NN, HH, 0, nullptr, s);
        float* t = hc; hc = hn; hn = t;
    }

    // --- pool + head ---
    pool_kernel<<<GG, HH, 0, s>>>(hc, gstart, gmean);
    launch_gemm(gmean, HH, nullptr, 0, HH, HH, head_w1, HH, head_b1, ghid, HH, GG, HH, 1, nullptr, s);
    launch_gemm(ghid, HH, nullptr, 0, HH, HH, head_w2, OUTD, head_b2, (float*)d_out, OUTD,
                GG, OUTD, 0, nullptr, s);
}